// round 12
// baseline (speedup 1.0000x reference)
#include <cuda_runtime.h>
#include <stdint.h>

// CornerActivationB: out[b, g*16+d] = bilinear interp of params[g, 0..3, d]
//   u_i = (clip(x_i,-1,1)+1)*0.5
//   out = (1-u0)(1-u1)P0 + (1-u0)u1 P1 + u0(1-u1)P2 + u0 u1 P3
//
// BATCH=8192, GROUPS=512, OUT_DIM=16.
// X: [8192,1024] f32, params: [512,4,16] f32, out: [8192,8192] f32.
//
// R12: TMA-bulk-store experiment. All prior configs (49.4-51.7us band,
// DRAM 57-62%) minted stores via per-lane STG.128 through L1tex. This
// version computes tiles into SMEM and drains them with cp.async.bulk
// shared->global (4 x 4KB contiguous rows per btile), double-buffered,
// with X loads for the next tile prefetched before the barrier.
// Falsification fork: neutral => DRAM write ceiling confirmed, R6 final;
// faster => store-path wavefronts were co-limiting.

#define GROUPS    512
#define OUT_DIM   16
#define BATCH     8192
#define GDIM      (GROUPS * OUT_DIM)   // 8192 floats per out row
#define XDIM      (GROUPS * 2)         // 1024 floats per X row
#define G_TILE    64
#define B_TILE    4
#define NBT       (BATCH / B_TILE)     // 2048 btiles per gtile
#define NCHUNK    74                   // 8 gtiles * 74 = 592 = 148 SMs * 4
#define ROW_BYTES (G_TILE * OUT_DIM * 4)   // 4096 B per (row, gtile) chunk

__global__ void __launch_bounds__(256, 4)
corner_act_kernel(const float* __restrict__ X,
                  const float* __restrict__ P,
                  float* __restrict__ out)
{
    // 2 stages x 4 rows x 4KB = 32KB static SMEM
    __shared__ __align__(16) float4 sbuf[2][B_TILE][256];

    const int tid   = threadIdx.x;
    const int q     = tid & 3;           // d-quad (0..3)
    const int gl    = tid >> 2;          // group within tile (0..63)
    const int gtile = blockIdx.x & 7;    // 0..7
    const int chunk = blockIdx.x >> 3;   // 0..73
    const int g     = gtile * G_TILE + gl;

    // params[g, j, d]: float4 index g*16 + j*4 + q  (loaded once per block)
    const float4* Pg = reinterpret_cast<const float4*>(P) + (size_t)g * 16;
    const float4 p0 = Pg[0 * 4 + q];
    const float4 p1 = Pg[1 * 4 + q];
    const float4 p2 = Pg[2 * 4 + q];
    const float4 p3 = Pg[3 * 4 + q];

    const float2* X2 = reinterpret_cast<const float2*>(X) + g;   // + b*(XDIM/2)
    const char*   Ob = reinterpret_cast<const char*>(out) + (size_t)gtile * ROW_BYTES;

    // Prologue: load X for the first btile.
    float2 xv[B_TILE];
    {
        const int b0 = chunk * B_TILE;
        #pragma unroll
        for (int r = 0; r < B_TILE; ++r)
            xv[r] = __ldg(X2 + (size_t)(b0 + r) * (XDIM / 2));
    }

    int stage = 0;
    for (int bt = chunk; bt < NBT; bt += NCHUNK) {
        // Compute current tile into SMEM. smem index = tid (gl*4+q): the
        // 256 float4s of each row are written conflict-free, fully packed.
        #pragma unroll
        for (int r = 0; r < B_TILE; ++r) {
            float u0 = (fminf(fmaxf(xv[r].x, -1.0f), 1.0f) + 1.0f) * 0.5f;
            float u1 = (fminf(fmaxf(xv[r].y, -1.0f), 1.0f) + 1.0f) * 0.5f;
            float v0 = 1.0f - u0;
            float v1 = 1.0f - u1;
            float c00 = v0 * v1;
            float c01 = v0 * u1;
            float c10 = u0 * v1;
            float c11 = u0 * u1;

            float4 o;
            o.x = c00 * p0.x + c01 * p1.x + c10 * p2.x + c11 * p3.x;
            o.y = c00 * p0.y + c01 * p1.y + c10 * p2.y + c11 * p3.y;
            o.z = c00 * p0.z + c01 * p1.z + c10 * p2.z + c11 * p3.z;
            o.w = c00 * p0.w + c01 * p1.w + c10 * p2.w + c11 * p3.w;

            sbuf[stage][r][tid] = o;
        }

        // Prefetch X for the next btile before the barrier (keeps DRAM load
        // latency off the barrier-serialized critical path).
        const int btn = bt + NCHUNK;
        if (btn < NBT) {
            const int bn0 = btn * B_TILE;
            #pragma unroll
            for (int r = 0; r < B_TILE; ++r)
                xv[r] = __ldg(X2 + (size_t)(bn0 + r) * (XDIM / 2));
        }

        __syncthreads();   // all STS for this stage complete

        if (tid == 0) {
            asm volatile("fence.proxy.async.shared::cta;" ::: "memory");
            const int b0 = bt * B_TILE;
            #pragma unroll
            for (int r = 0; r < B_TILE; ++r) {
                const char* dst = Ob + (size_t)(b0 + r) * (GDIM * 4);
                uint32_t src;
                asm("{ .reg .u64 t; cvta.to.shared.u64 t, %1; cvt.u32.u64 %0, t; }"
                    : "=r"(src) : "l"(&sbuf[stage][r][0]));
                asm volatile(
                    "cp.async.bulk.global.shared::cta.bulk_group [%0], [%1], %2;"
                    :: "l"(dst), "r"(src), "n"(ROW_BYTES) : "memory");
            }
            asm volatile("cp.async.bulk.commit_group;" ::: "memory");
            // Allow 1 group in flight: the buffer refilled next iter is the
            // one whose group (iter-1) is forced complete here.
            asm volatile("cp.async.bulk.wait_group 1;" ::: "memory");
        }

        __syncthreads();   // buffer-free guarantee visible to all threads
        stage ^= 1;
    }

    // Drain outstanding bulk stores before CTA exit.
    if (tid == 0)
        asm volatile("cp.async.bulk.wait_group 0;" ::: "memory");
}

extern "C" void kernel_launch(void* const* d_in, const int* in_sizes, int n_in,
                              void* d_out, int out_size)
{
    const float* X = (const float*)d_in[0];
    const float* P = (const float*)d_in[1];
    float* out = (float*)d_out;

    dim3 grid(8 * NCHUNK);   // 592 blocks = one wave at 4 blocks/SM
    dim3 block(256);
    corner_act_kernel<<<grid, block>>>(X, P, out);
}

// round 13
// speedup vs baseline: 1.1186x; 1.1186x over previous
#include <cuda_runtime.h>
#include <stdint.h>

// CornerActivationB: out[b, g*16+d] = bilinear interp of params[g, 0..3, d]
//   u_i = (clip(x_i,-1,1)+1)*0.5
//   out = (1-u0)(1-u1)P0 + (1-u0)u1 P1 + u0(1-u1)P2 + u0 u1 P3
//
// BATCH=8192, GROUPS=512, OUT_DIM=16.
// X: [8192,1024] f32, params: [512,4,16] f32, out: [8192,8192] f32.
//
// R13 = R6 (session best: persistent single wave, B_TILE=4 contiguous rows,
// register-resident params, 512B/warp STG.128) + uniform main loop.
// R6 tail: 24/92 chunks ran 23 btiles vs 22 (3.3% skew). Here every chunk
// runs exactly 22 btiles (92*22 = 2024 tiles = rows [0,8096)); the remaining
// 96 rows are distributed row-granular (1 row/block, 4 blocks take 2) ->
// 1.1% skew, zero atomics/extra barriers.
// Session-established facts: HBM write ceiling ~5.2 TB/s binds (STG vs TMA
// bulk, occ 44-68%, width, hints, density all falsified).

#define GROUPS    512
#define OUT_DIM   16
#define BATCH     8192
#define GDIM      (GROUPS * OUT_DIM)   // 8192
#define XDIM      (GROUPS * 2)         // 1024
#define G_TILE    64
#define B_TILE    4
#define NCHUNK    92                   // 8*92 = 736 blocks = one wave @ 5/SM
#define MAIN_IT   22                   // uniform iters: 92*22*4 = 8096 rows
#define REM_BASE  (NCHUNK * MAIN_IT * B_TILE)   // 8096
#define REM_ROWS  (BATCH - REM_BASE)            // 96

__global__ void __launch_bounds__(256, 5)
corner_act_kernel(const float* __restrict__ X,
                  const float* __restrict__ P,
                  float* __restrict__ out)
{
    const int tid   = threadIdx.x;
    const int q     = tid & 3;           // d-quad (0..3)
    const int gl    = tid >> 2;          // group within tile (0..63)
    const int gtile = blockIdx.x & 7;    // 0..7
    const int chunk = blockIdx.x >> 3;   // 0..91
    const int g     = gtile * G_TILE + gl;

    // params[g, j, d]: float4 index g*16 + j*4 + q  (loaded once per block)
    const float4* Pg = reinterpret_cast<const float4*>(P) + (size_t)g * 16;
    const float4 p0 = Pg[0 * 4 + q];
    const float4 p1 = Pg[1 * 4 + q];
    const float4 p2 = Pg[2 * 4 + q];
    const float4 p3 = Pg[3 * 4 + q];

    const float2* X2 = reinterpret_cast<const float2*>(X) + g;   // + b*(XDIM/2)
    float*        O  = out + (size_t)g * OUT_DIM + q * 4;        // + b*GDIM

    // Main loop: exactly MAIN_IT contiguous 4-row tiles per block.
    for (int i = 0; i < MAIN_IT; ++i) {
        const int b0 = (chunk + i * NCHUNK) * B_TILE;

        #pragma unroll
        for (int r = 0; r < B_TILE; ++r) {
            const int b = b0 + r;
            float2 xv = __ldg(X2 + (size_t)b * (XDIM / 2));  // 4-way broadcast
            float u0 = (fminf(fmaxf(xv.x, -1.0f), 1.0f) + 1.0f) * 0.5f;
            float u1 = (fminf(fmaxf(xv.y, -1.0f), 1.0f) + 1.0f) * 0.5f;
            float v0 = 1.0f - u0;
            float v1 = 1.0f - u1;
            float c00 = v0 * v1;
            float c01 = v0 * u1;
            float c10 = u0 * v1;
            float c11 = u0 * u1;

            float4 o;
            o.x = c00 * p0.x + c01 * p1.x + c10 * p2.x + c11 * p3.x;
            o.y = c00 * p0.y + c01 * p1.y + c10 * p2.y + c11 * p3.y;
            o.z = c00 * p0.z + c01 * p1.z + c10 * p2.z + c11 * p3.z;
            o.w = c00 * p0.w + c01 * p1.w + c10 * p2.w + c11 * p3.w;

            *reinterpret_cast<float4*>(O + (size_t)b * GDIM) = o;
        }
    }

    // Remainder: 96 rows [8096, 8192), row-granular, 1-2 per block.
    #pragma unroll
    for (int e = 0; e < 2; ++e) {
        const int b = REM_BASE + chunk + e * NCHUNK;
        if (b < BATCH) {
            float2 xv = __ldg(X2 + (size_t)b * (XDIM / 2));
            float u0 = (fminf(fmaxf(xv.x, -1.0f), 1.0f) + 1.0f) * 0.5f;
            float u1 = (fminf(fmaxf(xv.y, -1.0f), 1.0f) + 1.0f) * 0.5f;
            float v0 = 1.0f - u0;
            float v1 = 1.0f - u1;
            float c00 = v0 * v1;
            float c01 = v0 * u1;
            float c10 = u0 * v1;
            float c11 = u0 * u1;

            float4 o;
            o.x = c00 * p0.x + c01 * p1.x + c10 * p2.x + c11 * p3.x;
            o.y = c00 * p0.y + c01 * p1.y + c10 * p2.y + c11 * p3.y;
            o.z = c00 * p0.z + c01 * p1.z + c10 * p2.z + c11 * p3.z;
            o.w = c00 * p0.w + c01 * p1.w + c10 * p2.w + c11 * p3.w;

            *reinterpret_cast<float4*>(O + (size_t)b * GDIM) = o;
        }
    }
}

extern "C" void kernel_launch(void* const* d_in, const int* in_sizes, int n_in,
                              void* d_out, int out_size)
{
    const float* X = (const float*)d_in[0];
    const float* P = (const float*)d_in[1];
    float* out = (float*)d_out;

    dim3 grid(8 * NCHUNK);   // 736 blocks = one wave at 5 blocks/SM
    dim3 block(256);
    corner_act_kernel<<<grid, block>>>(X, P, out);
}